// round 9
// baseline (speedup 1.0000x reference)
#include <cuda_runtime.h>

// Problem constants
#define BB    16
#define MM    4096
#define KNB   16          // nsample
#define CMID  64          // c_out/2
#define COUT  128
#define NPTS  (BB*MM)     // 65536 points
#define NPOS  (NPTS*KNB)  // 1048576 BN positions
#define EPSF  1e-5f
#define SPB   64          // stats points per block
#define NSB   (NPTS/SPB)  // 1024 stats blocks

// Scratch (static device globals — no runtime allocation)
__device__ int   g_idx[NPOS];            // 4 MB  per-cloud neighbor indices (0..4095)
__device__ float g_u[NPTS*CMID];         // 16 MB u_j = [p_j,x_j] @ w1
__device__ float g_v[NPTS*CMID];         // 16 MB v_i = p_i @ w1[0:3]
__device__ float g_partial[NSB*128];     // per-block [sum(64) | sumsq(64)]
__device__ float g_scale[CMID];
__device__ float g_shift[CMID];
__device__ unsigned int g_tick;          // zero-init; reset by last block each call

// ---------------- packed f32x2 helpers ----------------
__device__ __forceinline__ unsigned long long packf2(float x) {
    unsigned long long r;
    asm("mov.b64 %0, {%1, %1};" : "=l"(r) : "r"(__float_as_uint(x)));
    return r;
}
__device__ __forceinline__ unsigned long long fma2(unsigned long long a,
                                                   unsigned long long b,
                                                   unsigned long long c) {
    unsigned long long d;
    asm("fma.rn.f32x2 %0, %1, %2, %3;" : "=l"(d) : "l"(a), "l"(b), "l"(c));
    return d;
}
__device__ __forceinline__ void unpack2(unsigned long long v, float& lo, float& hi) {
    unsigned int a, b;
    asm("mov.b64 {%0, %1}, %2;" : "=r"(a), "=r"(b) : "l"(v));
    lo = __uint_as_float(a); hi = __uint_as_float(b);
}

// ---------------- K1: KNN (top-16 smallest d2 per point, self included) ----------------
// Two-tier branch-free insert: most triggering candidates land in the bottom 4
// slots (20 predicated instrs); full 16-level bubble only when d < dk[11].
__global__ void knn_kernel(const float* __restrict__ p) {
    __shared__ __align__(16) float4 sp[1024];   // (x, y, z, |p|^2)
    const int cloud = blockIdx.y;
    const int q     = blockIdx.x * 128 + threadIdx.x;
    const int gi    = cloud * MM + q;

    const float qx = p[gi*3+0], qy = p[gi*3+1], qz = p[gi*3+2];
    const float qx2 = -2.f*qx, qy2 = -2.f*qy, qz2 = -2.f*qz;

    float dk[KNB]; int ik[KNB];
    #pragma unroll
    for (int t = 0; t < KNB; t++) { dk[t] = 3.0e38f; ik[t] = 0; }

    for (int t0 = 0; t0 < MM; t0 += 1024) {
        for (int jj = threadIdx.x; jj < 1024; jj += 128) {
            const int gj = cloud * MM + t0 + jj;
            float a = p[gj*3+0], b = p[gj*3+1], c = p[gj*3+2];
            sp[jj] = make_float4(a, b, c, a*a + b*b + c*c);
        }
        __syncthreads();
        #pragma unroll 4
        for (int jj = 0; jj < 1024; jj++) {
            const float4 s = sp[jj];
            float d = fmaf(qx2, s.x, fmaf(qy2, s.y, fmaf(qz2, s.z, s.w)));
            if (d < dk[KNB-1]) {
                float cd = d; int ci = t0 + jj;
                if (d < dk[11]) {
                    // deep (rare): full 16-level predicated bubble
                    #pragma unroll
                    for (int t = 0; t < KNB; t++) {
                        const float lo  = fminf(cd, dk[t]);
                        const float hiv = fmaxf(cd, dk[t]);
                        const bool  sw  = cd < dk[t];
                        const int   niv = sw ? ik[t] : ci;
                        ik[t] = sw ? ci : ik[t];
                        dk[t] = lo;
                        cd = hiv; ci = niv;
                    }
                } else {
                    // shallow (common): bubble only slots 12..15
                    #pragma unroll
                    for (int t = 12; t < KNB; t++) {
                        const float lo  = fminf(cd, dk[t]);
                        const float hiv = fmaxf(cd, dk[t]);
                        const bool  sw  = cd < dk[t];
                        const int   niv = sw ? ik[t] : ci;
                        ik[t] = sw ? ci : ik[t];
                        dk[t] = lo;
                        cd = hiv; ci = niv;
                    }
                }
            }
        }
        __syncthreads();
    }
    #pragma unroll
    for (int t = 0; t < KNB; t++) g_idx[gi*KNB + t] = ik[t];
}

// ---------------- K2: u = [p,x] @ w1 (67x64), v = p @ w1[0:3] ----------------
// 64 rows per block, 256 threads, thread = (row, 16-channel slab)
__global__ void uv_kernel(const float* __restrict__ p, const float* __restrict__ x,
                          const float* __restrict__ w1) {
    __shared__ __align__(16) float ws[67*64];
    __shared__ float as[64*68];
    const int tid  = threadIdx.x;
    const int row0 = blockIdx.x * 64;

    for (int i = tid; i < 67*64; i += 256) ws[i] = w1[i];
    for (int i = tid; i < 64*3; i += 256) {
        int rl = i / 3, cc = i % 3;
        as[rl*68 + cc] = p[(row0 + rl)*3 + cc];
    }
    for (int i = tid; i < 64*64; i += 256) {
        int rl = i >> 6, cc = i & 63;
        as[rl*68 + 3 + cc] = x[(row0 + rl)*64 + cc];
    }
    __syncthreads();

    const int rl = tid >> 2;
    const int c0 = (tid & 3) * 16;
    float acc[16];
    #pragma unroll
    for (int d = 0; d < 16; d++) acc[d] = 0.f;

    #pragma unroll
    for (int c = 0; c < 3; c++) {                 // xyz part -> becomes v
        float a = as[rl*68 + c];
        const float4* wp = (const float4*)&ws[c*64 + c0];
        #pragma unroll
        for (int d4 = 0; d4 < 4; d4++) {
            float4 w = wp[d4];
            acc[d4*4+0] = fmaf(a, w.x, acc[d4*4+0]);
            acc[d4*4+1] = fmaf(a, w.y, acc[d4*4+1]);
            acc[d4*4+2] = fmaf(a, w.z, acc[d4*4+2]);
            acc[d4*4+3] = fmaf(a, w.w, acc[d4*4+3]);
        }
    }
    float vac[16];
    #pragma unroll
    for (int d = 0; d < 16; d++) vac[d] = acc[d];

    for (int c = 3; c < 67; c++) {                // feature part
        float a = as[rl*68 + c];
        const float4* wp = (const float4*)&ws[c*64 + c0];
        #pragma unroll
        for (int d4 = 0; d4 < 4; d4++) {
            float4 w = wp[d4];
            acc[d4*4+0] = fmaf(a, w.x, acc[d4*4+0]);
            acc[d4*4+1] = fmaf(a, w.y, acc[d4*4+1]);
            acc[d4*4+2] = fmaf(a, w.z, acc[d4*4+2]);
            acc[d4*4+3] = fmaf(a, w.w, acc[d4*4+3]);
        }
    }
    const int grow = row0 + rl;
    float4* up = (float4*)&g_u[grow*64 + c0];
    float4* vp = (float4*)&g_v[grow*64 + c0];
    #pragma unroll
    for (int d4 = 0; d4 < 4; d4++) {
        up[d4] = make_float4(acc[d4*4], acc[d4*4+1], acc[d4*4+2], acc[d4*4+3]);
        vp[d4] = make_float4(vac[d4*4], vac[d4*4+1], vac[d4*4+2], vac[d4*4+3]);
    }
}

// ---------------- K3: BN statistics + fused final reduce (last-block pattern) ----
// 64 points/block, 256 threads, thread = (point, 16-channel slab)
__global__ void stats_kernel(const float* __restrict__ gamma,
                             const float* __restrict__ beta) {
    __shared__ float s_sum[SPB*64];
    __shared__ float s_ss[SPB*64];
    __shared__ bool  s_last;
    const int tid  = threadIdx.x;
    const int pt   = tid >> 2;
    const int c0   = (tid & 3) * 16;
    const int i    = blockIdx.x * SPB + pt;
    const int cloud = i >> 12;

    float4 v4[4];
    #pragma unroll
    for (int q = 0; q < 4; q++) v4[q] = *(const float4*)&g_v[i*64 + c0 + q*4];

    float sum[16], ss[16];
    #pragma unroll
    for (int d = 0; d < 16; d++) { sum[d] = 0.f; ss[d] = 0.f; }

    #pragma unroll 4
    for (int kk = 0; kk < KNB; kk++) {
        int j = g_idx[i*KNB + kk];
        const float4* up = (const float4*)&g_u[((cloud << 12) + j)*64 + c0];
        #pragma unroll
        for (int q = 0; q < 4; q++) {
            float4 u4 = up[q];
            float h0 = u4.x - v4[q].x, h1 = u4.y - v4[q].y;
            float h2 = u4.z - v4[q].z, h3 = u4.w - v4[q].w;
            sum[q*4+0] += h0; sum[q*4+1] += h1; sum[q*4+2] += h2; sum[q*4+3] += h3;
            ss[q*4+0] += h0*h0; ss[q*4+1] += h1*h1; ss[q*4+2] += h2*h2; ss[q*4+3] += h3*h3;
        }
    }
    #pragma unroll
    for (int d = 0; d < 16; d++) {
        s_sum[pt*64 + c0 + d] = sum[d];
        s_ss [pt*64 + c0 + d] = ss[d];
    }
    __syncthreads();

    if (tid < 128) {
        const int ch  = tid & 63;
        const bool hi = tid >= 64;
        float a = 0.f;
        #pragma unroll 8
        for (int p2 = 0; p2 < SPB; p2++)
            a += hi ? s_ss[p2*64 + ch] : s_sum[p2*64 + ch];
        g_partial[blockIdx.x*128 + tid] = a;
    }
    __threadfence();
    __syncthreads();
    if (tid == 0) s_last = (atomicAdd(&g_tick, 1u) == (unsigned)(NSB - 1));
    __syncthreads();
    if (!s_last) return;

    // Final reduce: 256 threads = 128 columns x 2 row-groups, coalesced rows.
    {
        const int col = tid & 127;
        const int grp = tid >> 7;
        float a = 0.f;
        #pragma unroll 8
        for (int r = grp * (NSB/2); r < (grp + 1) * (NSB/2); r++)
            a += g_partial[r*128 + col];
        s_sum[grp*128 + col] = a;
    }
    __syncthreads();
    if (tid < 64) {
        const float inv_n = 1.f / (float)NPOS;
        float mean = (s_sum[tid]      + s_sum[128 + tid]) * inv_n;
        float sq   = (s_sum[64 + tid] + s_sum[192 + tid]) * inv_n;
        float var  = sq - mean*mean;
        float sc   = gamma[tid] * rsqrtf(var + EPSF);
        g_scale[tid] = sc;
        g_shift[tid] = beta[tid] - mean * sc;
    }
    if (tid == 0) g_tick = 0u;   // reset for next graph replay
}

// ---------------- K4: fused BN+ReLU + GEMM2 (64->128) + maxpool over k ----------------
// Round-3 form; ONLY change: B loaded via ulonglong2 (LDS.128) — 4 LDS/k-step not 6.
__global__ void __launch_bounds__(256) out_kernel(const float* __restrict__ w2,
                                                  const float* __restrict__ b2,
                                                  float* __restrict__ out) {
    extern __shared__ float sm[];
    float* w2s  = sm;           // 8192: w2 [64][128]
    float* hs   = sm + 8192;    // 8192: h_bn k-major [64][128 rows]
    float* part = sm + 16384;   // 2048: partial row-maxes [16][128]
    float* ssc  = sm + 18432;   // 64
    float* ssh  = sm + 18496;   // 64

    const int t = threadIdx.x;
    for (int i = t; i < 8192; i += 256) w2s[i] = w2[i];
    if (t < 64)        ssc[t]      = g_scale[t];
    else if (t < 128)  ssh[t - 64] = g_shift[t - 64];
    __syncthreads();

    // Stage 1: build BN+ReLU'd h tile. thread -> (row = t>>1, 32-channel half)
    {
        const int row = t >> 1;
        const int c0  = (t & 1) * 32;
        const int ptl = row >> 4;
        const int kk  = row & 15;
        const int i   = blockIdx.x * 8 + ptl;
        const int cloud = i >> 12;
        const int j   = g_idx[i*KNB + kk];
        const int ur  = (cloud << 12) + j;
        const float4* up = (const float4*)&g_u[ur*64 + c0];
        const float4* vp = (const float4*)&g_v[i*64 + c0];
        #pragma unroll
        for (int q = 0; q < 8; q++) {
            float4 uu = up[q];
            float4 vv = vp[q];
            int c = c0 + q*4;
            hs[(c+0)*128 + row] = fmaxf(fmaf(ssc[c+0], uu.x - vv.x, ssh[c+0]), 0.f);
            hs[(c+1)*128 + row] = fmaxf(fmaf(ssc[c+1], uu.y - vv.y, ssh[c+1]), 0.f);
            hs[(c+2)*128 + row] = fmaxf(fmaf(ssc[c+2], uu.z - vv.z, ssh[c+2]), 0.f);
            hs[(c+3)*128 + row] = fmaxf(fmaf(ssc[c+3], uu.w - vv.w, ssh[c+3]), 0.f);
        }
    }
    __syncthreads();

    // Stage 2: 128x128x64 GEMM, 8 rows x 8 cols per thread, packed f32x2
    const int ty = t >> 4, tx = t & 15;
    unsigned long long acc[8][4];
    #pragma unroll
    for (int r = 0; r < 8; r++)
        #pragma unroll
        for (int cc = 0; cc < 4; cc++) acc[r][cc] = 0ull;

    const float* ha = hs  + ty*8;
    const float* wb = w2s + tx*8;
    for (int c = 0; c < 64; c++) {
        float4 a0 = *(const float4*)(ha + c*128);
        float4 a1 = *(const float4*)(ha + c*128 + 4);
        unsigned long long aa[8];
        aa[0] = packf2(a0.x); aa[1] = packf2(a0.y); aa[2] = packf2(a0.z); aa[3] = packf2(a0.w);
        aa[4] = packf2(a1.x); aa[5] = packf2(a1.y); aa[6] = packf2(a1.z); aa[7] = packf2(a1.w);
        const ulonglong2* bp = (const ulonglong2*)(wb + c*128);
        const ulonglong2 bA = bp[0];
        const ulonglong2 bB = bp[1];
        const unsigned long long b0 = bA.x, b1 = bA.y, bq2 = bB.x, b3 = bB.y;
        #pragma unroll
        for (int r = 0; r < 8; r++) {
            acc[r][0] = fma2(aa[r], b0,  acc[r][0]);
            acc[r][1] = fma2(aa[r], b1,  acc[r][1]);
            acc[r][2] = fma2(aa[r], bq2, acc[r][2]);
            acc[r][3] = fma2(aa[r], b3,  acc[r][3]);
        }
    }

    // Stage 3: max over this thread's 8 rows (half of one point's k)
    float mc[8];
    #pragma unroll
    for (int cc = 0; cc < 4; cc++) { unpack2(acc[0][cc], mc[2*cc], mc[2*cc+1]); }
    #pragma unroll
    for (int r = 1; r < 8; r++) {
        #pragma unroll
        for (int cc = 0; cc < 4; cc++) {
            float lo, hi; unpack2(acc[r][cc], lo, hi);
            mc[2*cc]   = fmaxf(mc[2*cc],   lo);
            mc[2*cc+1] = fmaxf(mc[2*cc+1], hi);
        }
    }
    float* pp = part + ty*128 + tx*8;
    *(float4*)(pp)     = make_float4(mc[0], mc[1], mc[2], mc[3]);
    *(float4*)(pp + 4) = make_float4(mc[4], mc[5], mc[6], mc[7]);
    __syncthreads();

    // Stage 4: combine the two half-point maxes, add bias, store
    if ((ty & 1) == 0) {
        const int oi = blockIdx.x * 8 + (ty >> 1);
        const float* pa = part + ty*128 + tx*8;
        const float* pb = pa + 128;
        float o[8];
        #pragma unroll
        for (int cc = 0; cc < 8; cc++)
            o[cc] = fmaxf(pa[cc], pb[cc]) + __ldg(&b2[tx*8 + cc]);
        float4* op = (float4*)&out[oi*128 + tx*8];
        op[0] = make_float4(o[0], o[1], o[2], o[3]);
        op[1] = make_float4(o[4], o[5], o[6], o[7]);
    }
}

// ---------------- launcher ----------------
extern "C" void kernel_launch(void* const* d_in, const int* in_sizes, int n_in,
                              void* d_out, int out_size) {
    const float* p     = (const float*)d_in[0];
    const float* x     = (const float*)d_in[1];
    const float* w1    = (const float*)d_in[2];
    const float* gamma = (const float*)d_in[3];
    const float* beta  = (const float*)d_in[4];
    const float* w2    = (const float*)d_in[5];
    const float* b2    = (const float*)d_in[6];
    float* out = (float*)d_out;

    (void)in_sizes; (void)n_in; (void)out_size;

    cudaFuncSetAttribute(out_kernel, cudaFuncAttributeMaxDynamicSharedMemorySize, 74240);

    knn_kernel<<<dim3(MM/128, BB), 128>>>(p);
    uv_kernel<<<NPTS/64, 256>>>(p, x, w1);
    stats_kernel<<<NSB, 256>>>(gamma, beta);
    out_kernel<<<NPTS/8, 256, 74240>>>(w2, b2, out);
}

// round 10
// speedup vs baseline: 1.1125x; 1.1125x over previous
#include <cuda_runtime.h>
#include <cstdint>

// Problem constants
#define BB    16
#define MM    4096
#define KNB   16          // nsample
#define CMID  64          // c_out/2
#define COUT  128
#define NPTS  (BB*MM)     // 65536 points
#define NPOS  (NPTS*KNB)  // 1048576 BN positions
#define EPSF  1e-5f
#define SPB   64          // stats points per block
#define NSB   (NPTS/SPB)  // 1024 stats blocks

// Scratch (static device globals — no runtime allocation)
__device__ int   g_idx[NPOS];            // 4 MB  per-cloud neighbor indices (0..4095)
__device__ float g_u[NPTS*CMID];         // 16 MB u_j = [p_j,x_j] @ w1
__device__ float g_v[NPTS*CMID];         // 16 MB v_i = p_i @ w1[0:3]
__device__ float g_partial[NSB*128];     // per-block [sum(64) | sumsq(64)]
__device__ float g_scale[CMID];
__device__ float g_shift[CMID];
__device__ unsigned int g_tick;          // zero-init; reset by last block each call

// ---------------- tf32 helpers ----------------
__device__ __forceinline__ uint32_t f2tf32(float f) {
    uint32_t u;
    asm("cvt.rna.tf32.f32 %0, %1;" : "=r"(u) : "f"(f));
    return u;
}
__device__ __forceinline__ void mma_tf32(float* d,
                                         uint32_t a0, uint32_t a1, uint32_t a2, uint32_t a3,
                                         uint32_t b0, uint32_t b1) {
    asm volatile(
        "mma.sync.aligned.m16n8k8.row.col.f32.tf32.tf32.f32 "
        "{%0,%1,%2,%3}, {%4,%5,%6,%7}, {%8,%9}, {%0,%1,%2,%3};"
        : "+f"(d[0]), "+f"(d[1]), "+f"(d[2]), "+f"(d[3])
        : "r"(a0), "r"(a1), "r"(a2), "r"(a3), "r"(b0), "r"(b1));
}

// ---------------- K1: KNN (top-16 smallest d2 per point, self included) ----------------
// Round-8 version (1214us config): branch-free full 16-level predicated bubble.
__global__ void knn_kernel(const float* __restrict__ p) {
    __shared__ __align__(16) float4 sp[1024];   // (x, y, z, |p|^2)
    const int cloud = blockIdx.y;
    const int q     = blockIdx.x * 128 + threadIdx.x;
    const int gi    = cloud * MM + q;

    const float qx = p[gi*3+0], qy = p[gi*3+1], qz = p[gi*3+2];
    const float qx2 = -2.f*qx, qy2 = -2.f*qy, qz2 = -2.f*qz;

    float dk[KNB]; int ik[KNB];
    #pragma unroll
    for (int t = 0; t < KNB; t++) { dk[t] = 3.0e38f; ik[t] = 0; }

    for (int t0 = 0; t0 < MM; t0 += 1024) {
        for (int jj = threadIdx.x; jj < 1024; jj += 128) {
            const int gj = cloud * MM + t0 + jj;
            float a = p[gj*3+0], b = p[gj*3+1], c = p[gj*3+2];
            sp[jj] = make_float4(a, b, c, a*a + b*b + c*c);
        }
        __syncthreads();
        #pragma unroll 4
        for (int jj = 0; jj < 1024; jj++) {
            const float4 s = sp[jj];
            float d = fmaf(qx2, s.x, fmaf(qy2, s.y, fmaf(qz2, s.z, s.w)));
            if (d < dk[KNB-1]) {
                float cd = d; int ci = t0 + jj;
                #pragma unroll
                for (int t = 0; t < KNB; t++) {
                    const float lo  = fminf(cd, dk[t]);
                    const float hiv = fmaxf(cd, dk[t]);
                    const bool  sw  = cd < dk[t];
                    const int   niv = sw ? ik[t] : ci;
                    ik[t] = sw ? ci : ik[t];
                    dk[t] = lo;
                    cd = hiv; ci = niv;
                }
            }
        }
        __syncthreads();
    }
    #pragma unroll
    for (int t = 0; t < KNB; t++) g_idx[gi*KNB + t] = ik[t];
}

// ---------------- K2: u = [p,x] @ w1 (67x64), v = p @ w1[0:3] ----------------
__global__ void uv_kernel(const float* __restrict__ p, const float* __restrict__ x,
                          const float* __restrict__ w1) {
    __shared__ __align__(16) float ws[67*64];
    __shared__ float as[64*68];
    const int tid  = threadIdx.x;
    const int row0 = blockIdx.x * 64;

    for (int i = tid; i < 67*64; i += 256) ws[i] = w1[i];
    for (int i = tid; i < 64*3; i += 256) {
        int rl = i / 3, cc = i % 3;
        as[rl*68 + cc] = p[(row0 + rl)*3 + cc];
    }
    for (int i = tid; i < 64*64; i += 256) {
        int rl = i >> 6, cc = i & 63;
        as[rl*68 + 3 + cc] = x[(row0 + rl)*64 + cc];
    }
    __syncthreads();

    const int rl = tid >> 2;
    const int c0 = (tid & 3) * 16;
    float acc[16];
    #pragma unroll
    for (int d = 0; d < 16; d++) acc[d] = 0.f;

    #pragma unroll
    for (int c = 0; c < 3; c++) {                 // xyz part -> becomes v
        float a = as[rl*68 + c];
        const float4* wp = (const float4*)&ws[c*64 + c0];
        #pragma unroll
        for (int d4 = 0; d4 < 4; d4++) {
            float4 w = wp[d4];
            acc[d4*4+0] = fmaf(a, w.x, acc[d4*4+0]);
            acc[d4*4+1] = fmaf(a, w.y, acc[d4*4+1]);
            acc[d4*4+2] = fmaf(a, w.z, acc[d4*4+2]);
            acc[d4*4+3] = fmaf(a, w.w, acc[d4*4+3]);
        }
    }
    float vac[16];
    #pragma unroll
    for (int d = 0; d < 16; d++) vac[d] = acc[d];

    for (int c = 3; c < 67; c++) {                // feature part
        float a = as[rl*68 + c];
        const float4* wp = (const float4*)&ws[c*64 + c0];
        #pragma unroll
        for (int d4 = 0; d4 < 4; d4++) {
            float4 w = wp[d4];
            acc[d4*4+0] = fmaf(a, w.x, acc[d4*4+0]);
            acc[d4*4+1] = fmaf(a, w.y, acc[d4*4+1]);
            acc[d4*4+2] = fmaf(a, w.z, acc[d4*4+2]);
            acc[d4*4+3] = fmaf(a, w.w, acc[d4*4+3]);
        }
    }
    const int grow = row0 + rl;
    float4* up = (float4*)&g_u[grow*64 + c0];
    float4* vp = (float4*)&g_v[grow*64 + c0];
    #pragma unroll
    for (int d4 = 0; d4 < 4; d4++) {
        up[d4] = make_float4(acc[d4*4], acc[d4*4+1], acc[d4*4+2], acc[d4*4+3]);
        vp[d4] = make_float4(vac[d4*4], vac[d4*4+1], vac[d4*4+2], vac[d4*4+3]);
    }
}

// ---------------- K3: BN statistics + fused final reduce (last-block pattern) ----
__global__ void stats_kernel(const float* __restrict__ gamma,
                             const float* __restrict__ beta) {
    __shared__ float s_sum[SPB*64];
    __shared__ float s_ss[SPB*64];
    __shared__ bool  s_last;
    const int tid  = threadIdx.x;
    const int pt   = tid >> 2;
    const int c0   = (tid & 3) * 16;
    const int i    = blockIdx.x * SPB + pt;
    const int cloud = i >> 12;

    float4 v4[4];
    #pragma unroll
    for (int q = 0; q < 4; q++) v4[q] = *(const float4*)&g_v[i*64 + c0 + q*4];

    float sum[16], ss[16];
    #pragma unroll
    for (int d = 0; d < 16; d++) { sum[d] = 0.f; ss[d] = 0.f; }

    #pragma unroll 4
    for (int kk = 0; kk < KNB; kk++) {
        int j = g_idx[i*KNB + kk];
        const float4* up = (const float4*)&g_u[((cloud << 12) + j)*64 + c0];
        #pragma unroll
        for (int q = 0; q < 4; q++) {
            float4 u4 = up[q];
            float h0 = u4.x - v4[q].x, h1 = u4.y - v4[q].y;
            float h2 = u4.z - v4[q].z, h3 = u4.w - v4[q].w;
            sum[q*4+0] += h0; sum[q*4+1] += h1; sum[q*4+2] += h2; sum[q*4+3] += h3;
            ss[q*4+0] += h0*h0; ss[q*4+1] += h1*h1; ss[q*4+2] += h2*h2; ss[q*4+3] += h3*h3;
        }
    }
    #pragma unroll
    for (int d = 0; d < 16; d++) {
        s_sum[pt*64 + c0 + d] = sum[d];
        s_ss [pt*64 + c0 + d] = ss[d];
    }
    __syncthreads();

    if (tid < 128) {
        const int ch  = tid & 63;
        const bool hi = tid >= 64;
        float a = 0.f;
        #pragma unroll 8
        for (int p2 = 0; p2 < SPB; p2++)
            a += hi ? s_ss[p2*64 + ch] : s_sum[p2*64 + ch];
        g_partial[blockIdx.x*128 + tid] = a;
    }
    __threadfence();
    __syncthreads();
    if (tid == 0) s_last = (atomicAdd(&g_tick, 1u) == (unsigned)(NSB - 1));
    __syncthreads();
    if (!s_last) return;

    {
        const int col = tid & 127;
        const int grp = tid >> 7;
        float a = 0.f;
        #pragma unroll 8
        for (int r = grp * (NSB/2); r < (grp + 1) * (NSB/2); r++)
            a += g_partial[r*128 + col];
        s_sum[grp*128 + col] = a;
    }
    __syncthreads();
    if (tid < 64) {
        const float inv_n = 1.f / (float)NPOS;
        float mean = (s_sum[tid]      + s_sum[128 + tid]) * inv_n;
        float sq   = (s_sum[64 + tid] + s_sum[192 + tid]) * inv_n;
        float var  = sq - mean*mean;
        float sc   = gamma[tid] * rsqrtf(var + EPSF);
        g_scale[tid] = sc;
        g_shift[tid] = beta[tid] - mean * sc;
    }
    if (tid == 0) g_tick = 0u;   // reset for next graph replay
}

// ---------------- K4: fused BN+ReLU + GEMM2 (64->128) + maxpool via TF32 MMA ------
// 8 points/block, 256 threads = 8 warps; warp w <-> point w (its 16 h-rows).
// Per warp: K=64 in 8 chunks, N=128 in 16 tiles of m16n8k8 TF32 mma.sync.
// Padded (132) smem layouts make all fragment loads bank-conflict-free.
__global__ void __launch_bounds__(256) out_kernel(const float* __restrict__ w2,
                                                  const float* __restrict__ b2,
                                                  float* __restrict__ out) {
    extern __shared__ float sm[];
    uint32_t* w2s = (uint32_t*)sm;            // [64][132] tf32
    uint32_t* hs  = (uint32_t*)(sm + 8448);   // [64][132] tf32 (k-major: [c][row])
    float* ssc = sm + 16896;                  // 64
    float* ssh = sm + 16960;                  // 64

    const int t = threadIdx.x;
    for (int i = t; i < 8192; i += 256) {
        int k = i >> 7, n = i & 127;
        w2s[k*132 + n] = f2tf32(w2[i]);
    }
    if (t < 64)        ssc[t]      = g_scale[t];
    else if (t < 128)  ssh[t - 64] = g_shift[t - 64];
    __syncthreads();

    // Stage 1: build BN+ReLU'd h tile (tf32). thread -> (row = t>>1, 32-channel half)
    {
        const int row = t >> 1;
        const int c0  = (t & 1) * 32;
        const int ptl = row >> 4;
        const int kk  = row & 15;
        const int i   = blockIdx.x * 8 + ptl;
        const int cloud = i >> 12;
        const int j   = g_idx[i*KNB + kk];
        const int ur  = (cloud << 12) + j;
        const float4* up = (const float4*)&g_u[ur*64 + c0];
        const float4* vp = (const float4*)&g_v[i*64 + c0];
        #pragma unroll
        for (int q = 0; q < 8; q++) {
            float4 uu = up[q];
            float4 vv = vp[q];
            int c = c0 + q*4;
            hs[(c+0)*132 + row] = f2tf32(fmaxf(fmaf(ssc[c+0], uu.x - vv.x, ssh[c+0]), 0.f));
            hs[(c+1)*132 + row] = f2tf32(fmaxf(fmaf(ssc[c+1], uu.y - vv.y, ssh[c+1]), 0.f));
            hs[(c+2)*132 + row] = f2tf32(fmaxf(fmaf(ssc[c+2], uu.z - vv.z, ssh[c+2]), 0.f));
            hs[(c+3)*132 + row] = f2tf32(fmaxf(fmaf(ssc[c+3], uu.w - vv.w, ssh[c+3]), 0.f));
        }
    }
    __syncthreads();

    // Stage 2: per-warp 16x128x64 TF32 MMA
    const int w    = t >> 5;          // warp = local point
    const int lane = t & 31;
    const int grp  = lane >> 2;       // row group 0..7
    const int lid4 = lane & 3;        // k/col group 0..3
    const int rbase = w * 16;

    float acc[16][4];
    #pragma unroll
    for (int nt = 0; nt < 16; nt++)
        #pragma unroll
        for (int e = 0; e < 4; e++) acc[nt][e] = 0.f;

    #pragma unroll
    for (int kc = 0; kc < 8; kc++) {
        const int c0 = kc * 8;
        const uint32_t a0 = hs[(c0 + lid4    )*132 + rbase + grp    ];
        const uint32_t a1 = hs[(c0 + lid4    )*132 + rbase + grp + 8];
        const uint32_t a2 = hs[(c0 + lid4 + 4)*132 + rbase + grp    ];
        const uint32_t a3 = hs[(c0 + lid4 + 4)*132 + rbase + grp + 8];
        #pragma unroll
        for (int nt = 0; nt < 16; nt++) {
            const uint32_t b0 = w2s[(c0 + lid4    )*132 + nt*8 + grp];
            const uint32_t b1 = w2s[(c0 + lid4 + 4)*132 + nt*8 + grp];
            mma_tf32(acc[nt], a0, a1, a2, a3, b0, b1);
        }
    }

    // Stage 3: maxpool over the 16 rows (= the point's 16 neighbors)
    // Thread holds rows {grp, grp+8}; butterfly over lane bits 2..4 covers all grp.
    const int i = blockIdx.x * 8 + w;
    #pragma unroll
    for (int nt = 0; nt < 16; nt++) {
        float m0 = fmaxf(acc[nt][0], acc[nt][2]);
        float m1 = fmaxf(acc[nt][1], acc[nt][3]);
        #pragma unroll
        for (int mask = 4; mask <= 16; mask <<= 1) {
            m0 = fmaxf(m0, __shfl_xor_sync(0xFFFFFFFFu, m0, mask));
            m1 = fmaxf(m1, __shfl_xor_sync(0xFFFFFFFFu, m1, mask));
        }
        if (grp == 0) {
            const int col = nt*8 + 2*lid4;
            float2 o;
            o.x = m0 + __ldg(&b2[col]);
            o.y = m1 + __ldg(&b2[col + 1]);
            *(float2*)&out[i*128 + col] = o;
        }
    }
}

// ---------------- launcher ----------------
extern "C" void kernel_launch(void* const* d_in, const int* in_sizes, int n_in,
                              void* d_out, int out_size) {
    const float* p     = (const float*)d_in[0];
    const float* x     = (const float*)d_in[1];
    const float* w1    = (const float*)d_in[2];
    const float* gamma = (const float*)d_in[3];
    const float* beta  = (const float*)d_in[4];
    const float* w2    = (const float*)d_in[5];
    const float* b2    = (const float*)d_in[6];
    float* out = (float*)d_out;

    (void)in_sizes; (void)n_in; (void)out_size;

    // smem: 8448 (w2s) + 8448 (hs) + 64 + 64 = 17024 floats = 68096 B
    cudaFuncSetAttribute(out_kernel, cudaFuncAttributeMaxDynamicSharedMemorySize, 68096);

    knn_kernel<<<dim3(MM/128, BB), 128>>>(p);
    uv_kernel<<<NPTS/64, 256>>>(p, x, w1);
    stats_kernel<<<NSB, 256>>>(gamma, beta);
    out_kernel<<<NPTS/8, 256, 68096>>>(w2, b2, out);
}

// round 11
// speedup vs baseline: 1.1720x; 1.0535x over previous
#include <cuda_runtime.h>
#include <cstdint>

// Problem constants
#define BB    16
#define MM    4096
#define KNB   16          // nsample
#define CMID  64          // c_out/2
#define COUT  128
#define NPTS  (BB*MM)     // 65536 points
#define NPOS  (NPTS*KNB)  // 1048576 BN positions
#define EPSF  1e-5f
#define SPB   64          // stats points per block
#define NSB   (NPTS/SPB)  // 1024 stats blocks

// Scratch (static device globals — no runtime allocation)
__device__ int   g_idx[NPOS];            // 4 MB  per-cloud neighbor indices (0..4095)
__device__ float g_u[NPTS*CMID];         // 16 MB u_j = [p_j,x_j] @ w1
__device__ float g_v[NPTS*CMID];         // 16 MB v_i = p_i @ w1[0:3]
__device__ float g_partial[NSB*128];     // per-block [sum(64) | sumsq(64)]
__device__ float g_scale[CMID];
__device__ float g_shift[CMID];
__device__ unsigned int g_tick;          // zero-init; reset by last block each call

// ---------------- tf32 helpers ----------------
__device__ __forceinline__ uint32_t f2tf32(float f) {
    uint32_t u;
    asm("cvt.rna.tf32.f32 %0, %1;" : "=r"(u) : "f"(f));
    return u;
}
__device__ __forceinline__ void mma_tf32(float* d,
                                         uint32_t a0, uint32_t a1, uint32_t a2, uint32_t a3,
                                         uint32_t b0, uint32_t b1) {
    asm volatile(
        "mma.sync.aligned.m16n8k8.row.col.f32.tf32.tf32.f32 "
        "{%0,%1,%2,%3}, {%4,%5,%6,%7}, {%8,%9}, {%0,%1,%2,%3};"
        : "+f"(d[0]), "+f"(d[1]), "+f"(d[2]), "+f"(d[3])
        : "r"(a0), "r"(a1), "r"(a2), "r"(a3), "r"(b0), "r"(b1));
}

// Fragment-row stride: 136 mod 32 = 8 -> lane bank = 8*lid4 + grp, a bijection
// over lid4 in [0,4) x grp in [0,8): conflict-free fragment loads.
#define FSTRIDE 136

// ---------------- K1: KNN (top-16 smallest d2 per point, self included) ----------------
// Round-8 version (1214us config): branch-free full 16-level predicated bubble.
__global__ void knn_kernel(const float* __restrict__ p) {
    __shared__ __align__(16) float4 sp[1024];   // (x, y, z, |p|^2)
    const int cloud = blockIdx.y;
    const int q     = blockIdx.x * 128 + threadIdx.x;
    const int gi    = cloud * MM + q;

    const float qx = p[gi*3+0], qy = p[gi*3+1], qz = p[gi*3+2];
    const float qx2 = -2.f*qx, qy2 = -2.f*qy, qz2 = -2.f*qz;

    float dk[KNB]; int ik[KNB];
    #pragma unroll
    for (int t = 0; t < KNB; t++) { dk[t] = 3.0e38f; ik[t] = 0; }

    for (int t0 = 0; t0 < MM; t0 += 1024) {
        for (int jj = threadIdx.x; jj < 1024; jj += 128) {
            const int gj = cloud * MM + t0 + jj;
            float a = p[gj*3+0], b = p[gj*3+1], c = p[gj*3+2];
            sp[jj] = make_float4(a, b, c, a*a + b*b + c*c);
        }
        __syncthreads();
        #pragma unroll 4
        for (int jj = 0; jj < 1024; jj++) {
            const float4 s = sp[jj];
            float d = fmaf(qx2, s.x, fmaf(qy2, s.y, fmaf(qz2, s.z, s.w)));
            if (d < dk[KNB-1]) {
                float cd = d; int ci = t0 + jj;
                #pragma unroll
                for (int t = 0; t < KNB; t++) {
                    const float lo  = fminf(cd, dk[t]);
                    const float hiv = fmaxf(cd, dk[t]);
                    const bool  sw  = cd < dk[t];
                    const int   niv = sw ? ik[t] : ci;
                    ik[t] = sw ? ci : ik[t];
                    dk[t] = lo;
                    cd = hiv; ci = niv;
                }
            }
        }
        __syncthreads();
    }
    #pragma unroll
    for (int t = 0; t < KNB; t++) g_idx[gi*KNB + t] = ik[t];
}

// ---------------- K2: u = [p,x] @ w1 (67x64), v = p @ w1[0:3] ----------------
__global__ void uv_kernel(const float* __restrict__ p, const float* __restrict__ x,
                          const float* __restrict__ w1) {
    __shared__ __align__(16) float ws[67*64];
    __shared__ float as[64*68];
    const int tid  = threadIdx.x;
    const int row0 = blockIdx.x * 64;

    for (int i = tid; i < 67*64; i += 256) ws[i] = w1[i];
    for (int i = tid; i < 64*3; i += 256) {
        int rl = i / 3, cc = i % 3;
        as[rl*68 + cc] = p[(row0 + rl)*3 + cc];
    }
    for (int i = tid; i < 64*64; i += 256) {
        int rl = i >> 6, cc = i & 63;
        as[rl*68 + 3 + cc] = x[(row0 + rl)*64 + cc];
    }
    __syncthreads();

    const int rl = tid >> 2;
    const int c0 = (tid & 3) * 16;
    float acc[16];
    #pragma unroll
    for (int d = 0; d < 16; d++) acc[d] = 0.f;

    #pragma unroll
    for (int c = 0; c < 3; c++) {                 // xyz part -> becomes v
        float a = as[rl*68 + c];
        const float4* wp = (const float4*)&ws[c*64 + c0];
        #pragma unroll
        for (int d4 = 0; d4 < 4; d4++) {
            float4 w = wp[d4];
            acc[d4*4+0] = fmaf(a, w.x, acc[d4*4+0]);
            acc[d4*4+1] = fmaf(a, w.y, acc[d4*4+1]);
            acc[d4*4+2] = fmaf(a, w.z, acc[d4*4+2]);
            acc[d4*4+3] = fmaf(a, w.w, acc[d4*4+3]);
        }
    }
    float vac[16];
    #pragma unroll
    for (int d = 0; d < 16; d++) vac[d] = acc[d];

    for (int c = 3; c < 67; c++) {                // feature part
        float a = as[rl*68 + c];
        const float4* wp = (const float4*)&ws[c*64 + c0];
        #pragma unroll
        for (int d4 = 0; d4 < 4; d4++) {
            float4 w = wp[d4];
            acc[d4*4+0] = fmaf(a, w.x, acc[d4*4+0]);
            acc[d4*4+1] = fmaf(a, w.y, acc[d4*4+1]);
            acc[d4*4+2] = fmaf(a, w.z, acc[d4*4+2]);
            acc[d4*4+3] = fmaf(a, w.w, acc[d4*4+3]);
        }
    }
    const int grow = row0 + rl;
    float4* up = (float4*)&g_u[grow*64 + c0];
    float4* vp = (float4*)&g_v[grow*64 + c0];
    #pragma unroll
    for (int d4 = 0; d4 < 4; d4++) {
        up[d4] = make_float4(acc[d4*4], acc[d4*4+1], acc[d4*4+2], acc[d4*4+3]);
        vp[d4] = make_float4(vac[d4*4], vac[d4*4+1], vac[d4*4+2], vac[d4*4+3]);
    }
}

// ---------------- K3: BN statistics + fused final reduce (last-block pattern) ----
__global__ void stats_kernel(const float* __restrict__ gamma,
                             const float* __restrict__ beta) {
    __shared__ float s_sum[SPB*64];
    __shared__ float s_ss[SPB*64];
    __shared__ bool  s_last;
    const int tid  = threadIdx.x;
    const int pt   = tid >> 2;
    const int c0   = (tid & 3) * 16;
    const int i    = blockIdx.x * SPB + pt;
    const int cloud = i >> 12;

    float4 v4[4];
    #pragma unroll
    for (int q = 0; q < 4; q++) v4[q] = *(const float4*)&g_v[i*64 + c0 + q*4];

    float sum[16], ss[16];
    #pragma unroll
    for (int d = 0; d < 16; d++) { sum[d] = 0.f; ss[d] = 0.f; }

    #pragma unroll 4
    for (int kk = 0; kk < KNB; kk++) {
        int j = g_idx[i*KNB + kk];
        const float4* up = (const float4*)&g_u[((cloud << 12) + j)*64 + c0];
        #pragma unroll
        for (int q = 0; q < 4; q++) {
            float4 u4 = up[q];
            float h0 = u4.x - v4[q].x, h1 = u4.y - v4[q].y;
            float h2 = u4.z - v4[q].z, h3 = u4.w - v4[q].w;
            sum[q*4+0] += h0; sum[q*4+1] += h1; sum[q*4+2] += h2; sum[q*4+3] += h3;
            ss[q*4+0] += h0*h0; ss[q*4+1] += h1*h1; ss[q*4+2] += h2*h2; ss[q*4+3] += h3*h3;
        }
    }
    #pragma unroll
    for (int d = 0; d < 16; d++) {
        s_sum[pt*64 + c0 + d] = sum[d];
        s_ss [pt*64 + c0 + d] = ss[d];
    }
    __syncthreads();

    if (tid < 128) {
        const int ch  = tid & 63;
        const bool hi = tid >= 64;
        float a = 0.f;
        #pragma unroll 8
        for (int p2 = 0; p2 < SPB; p2++)
            a += hi ? s_ss[p2*64 + ch] : s_sum[p2*64 + ch];
        g_partial[blockIdx.x*128 + tid] = a;
    }
    __threadfence();
    __syncthreads();
    if (tid == 0) s_last = (atomicAdd(&g_tick, 1u) == (unsigned)(NSB - 1));
    __syncthreads();
    if (!s_last) return;

    {
        const int col = tid & 127;
        const int grp = tid >> 7;
        float a = 0.f;
        #pragma unroll 8
        for (int r = grp * (NSB/2); r < (grp + 1) * (NSB/2); r++)
            a += g_partial[r*128 + col];
        s_sum[grp*128 + col] = a;
    }
    __syncthreads();
    if (tid < 64) {
        const float inv_n = 1.f / (float)NPOS;
        float mean = (s_sum[tid]      + s_sum[128 + tid]) * inv_n;
        float sq   = (s_sum[64 + tid] + s_sum[192 + tid]) * inv_n;
        float var  = sq - mean*mean;
        float sc   = gamma[tid] * rsqrtf(var + EPSF);
        g_scale[tid] = sc;
        g_shift[tid] = beta[tid] - mean * sc;
    }
    if (tid == 0) g_tick = 0u;   // reset for next graph replay
}

// ---------------- K4: fused BN+ReLU + GEMM2 (64->128) + maxpool via TF32 MMA ------
// 8 points/block, 256 threads = 8 warps; warp w <-> point w (its 16 h-rows).
// Per warp: K=64 in 8 chunks, N=128 in 16 tiles of m16n8k8 TF32 mma.sync.
// FSTRIDE=136 makes all fragment loads bank-conflict-free (8*lid4+grp bijection).
__global__ void __launch_bounds__(256) out_kernel(const float* __restrict__ w2,
                                                  const float* __restrict__ b2,
                                                  float* __restrict__ out) {
    extern __shared__ float sm[];
    uint32_t* w2s = (uint32_t*)sm;                    // [64][FSTRIDE] tf32
    uint32_t* hs  = (uint32_t*)(sm + 64*FSTRIDE);     // [64][FSTRIDE] tf32 (k-major)
    float* ssc = sm + 2*64*FSTRIDE;                   // 64
    float* ssh = ssc + 64;                            // 64

    const int t = threadIdx.x;
    for (int i = t; i < 8192; i += 256) {
        int k = i >> 7, n = i & 127;
        w2s[k*FSTRIDE + n] = f2tf32(w2[i]);
    }
    if (t < 64)        ssc[t]      = g_scale[t];
    else if (t < 128)  ssh[t - 64] = g_shift[t - 64];
    __syncthreads();

    // Stage 1: build BN+ReLU'd h tile (tf32). thread -> (row = t>>1, 32-channel half)
    {
        const int row = t >> 1;
        const int c0  = (t & 1) * 32;
        const int ptl = row >> 4;
        const int kk  = row & 15;
        const int i   = blockIdx.x * 8 + ptl;
        const int cloud = i >> 12;
        const int j   = g_idx[i*KNB + kk];
        const int ur  = (cloud << 12) + j;
        const float4* up = (const float4*)&g_u[ur*64 + c0];
        const float4* vp = (const float4*)&g_v[i*64 + c0];
        #pragma unroll
        for (int q = 0; q < 8; q++) {
            float4 uu = up[q];
            float4 vv = vp[q];
            int c = c0 + q*4;
            hs[(c+0)*FSTRIDE + row] = f2tf32(fmaxf(fmaf(ssc[c+0], uu.x - vv.x, ssh[c+0]), 0.f));
            hs[(c+1)*FSTRIDE + row] = f2tf32(fmaxf(fmaf(ssc[c+1], uu.y - vv.y, ssh[c+1]), 0.f));
            hs[(c+2)*FSTRIDE + row] = f2tf32(fmaxf(fmaf(ssc[c+2], uu.z - vv.z, ssh[c+2]), 0.f));
            hs[(c+3)*FSTRIDE + row] = f2tf32(fmaxf(fmaf(ssc[c+3], uu.w - vv.w, ssh[c+3]), 0.f));
        }
    }
    __syncthreads();

    // Stage 2: per-warp 16x128x64 TF32 MMA
    const int w    = t >> 5;          // warp = local point
    const int lane = t & 31;
    const int grp  = lane >> 2;       // row group 0..7
    const int lid4 = lane & 3;        // k/col group 0..3
    const int rbase = w * 16;

    float acc[16][4];
    #pragma unroll
    for (int nt = 0; nt < 16; nt++)
        #pragma unroll
        for (int e = 0; e < 4; e++) acc[nt][e] = 0.f;

    #pragma unroll
    for (int kc = 0; kc < 8; kc++) {
        const int c0 = kc * 8;
        const uint32_t a0 = hs[(c0 + lid4    )*FSTRIDE + rbase + grp    ];
        const uint32_t a1 = hs[(c0 + lid4    )*FSTRIDE + rbase + grp + 8];
        const uint32_t a2 = hs[(c0 + lid4 + 4)*FSTRIDE + rbase + grp    ];
        const uint32_t a3 = hs[(c0 + lid4 + 4)*FSTRIDE + rbase + grp + 8];
        #pragma unroll
        for (int nt = 0; nt < 16; nt++) {
            const uint32_t b0 = w2s[(c0 + lid4    )*FSTRIDE + nt*8 + grp];
            const uint32_t b1 = w2s[(c0 + lid4 + 4)*FSTRIDE + nt*8 + grp];
            mma_tf32(acc[nt], a0, a1, a2, a3, b0, b1);
        }
    }

    // Stage 3: maxpool over the 16 rows (= the point's 16 neighbors)
    const int i = blockIdx.x * 8 + w;
    #pragma unroll
    for (int nt = 0; nt < 16; nt++) {
        float m0 = fmaxf(acc[nt][0], acc[nt][2]);
        float m1 = fmaxf(acc[nt][1], acc[nt][3]);
        #pragma unroll
        for (int mask = 4; mask <= 16; mask <<= 1) {
            m0 = fmaxf(m0, __shfl_xor_sync(0xFFFFFFFFu, m0, mask));
            m1 = fmaxf(m1, __shfl_xor_sync(0xFFFFFFFFu, m1, mask));
        }
        if (grp == 0) {
            const int col = nt*8 + 2*lid4;
            float2 o;
            o.x = m0 + __ldg(&b2[col]);
            o.y = m1 + __ldg(&b2[col + 1]);
            *(float2*)&out[i*128 + col] = o;
        }
    }
}

// ---------------- launcher ----------------
extern "C" void kernel_launch(void* const* d_in, const int* in_sizes, int n_in,
                              void* d_out, int out_size) {
    const float* p     = (const float*)d_in[0];
    const float* x     = (const float*)d_in[1];
    const float* w1    = (const float*)d_in[2];
    const float* gamma = (const float*)d_in[3];
    const float* beta  = (const float*)d_in[4];
    const float* w2    = (const float*)d_in[5];
    const float* b2    = (const float*)d_in[6];
    float* out = (float*)d_out;

    (void)in_sizes; (void)n_in; (void)out_size;

    // smem: 2*64*136 + 128 = 17536 floats = 70144 B
    cudaFuncSetAttribute(out_kernel, cudaFuncAttributeMaxDynamicSharedMemorySize, 70144);

    knn_kernel<<<dim3(MM/128, BB), 128>>>(p);
    uv_kernel<<<NPTS/64, 256>>>(p, x, w1);
    stats_kernel<<<NSB, 256>>>(gamma, beta);
    out_kernel<<<NPTS/8, 256, 70144>>>(w2, b2, out);
}

// round 12
// speedup vs baseline: 1.1950x; 1.0196x over previous
#include <cuda_runtime.h>
#include <cstdint>

// Problem constants
#define BB    16
#define MM    4096
#define KNB   16          // nsample
#define CMID  64          // c_out/2
#define COUT  128
#define NPTS  (BB*MM)     // 65536 points
#define NPOS  (NPTS*KNB)  // 1048576 BN positions
#define EPSF  1e-5f
#define SPB   64          // stats points per block
#define NSB   (NPTS/SPB)  // 1024 stats blocks

// Scratch (static device globals — no runtime allocation)
__device__ int   g_idx[NPOS];            // 4 MB  per-cloud neighbor indices (0..4095)
__device__ float g_u[NPTS*CMID];         // 16 MB u_j = [p_j,x_j] @ w1
__device__ float g_v[NPTS*CMID];         // 16 MB v_i = p_i @ w1[0:3]
__device__ float g_partial[NSB*128];     // per-block [sum(64) | sumsq(64)]
__device__ float g_scale[CMID];
__device__ float g_shift[CMID];
__device__ unsigned int g_tick;          // zero-init; reset by last block each call

// ---------------- tf32 helpers ----------------
__device__ __forceinline__ uint32_t f2tf32(float f) {
    uint32_t u;
    asm("cvt.rna.tf32.f32 %0, %1;" : "=r"(u) : "f"(f));
    return u;
}
__device__ __forceinline__ void mma_tf32(float* d,
                                         uint32_t a0, uint32_t a1, uint32_t a2, uint32_t a3,
                                         uint32_t b0, uint32_t b1) {
    asm volatile(
        "mma.sync.aligned.m16n8k8.row.col.f32.tf32.tf32.f32 "
        "{%0,%1,%2,%3}, {%4,%5,%6,%7}, {%8,%9}, {%0,%1,%2,%3};"
        : "+f"(d[0]), "+f"(d[1]), "+f"(d[2]), "+f"(d[3])
        : "r"(a0), "r"(a1), "r"(a2), "r"(a3), "r"(b0), "r"(b1));
}

// Fragment-row stride: 136 mod 32 = 8 -> lane bank = 8*lid4 + grp, a bijection
// over lid4 in [0,4) x grp in [0,8): conflict-free fragment loads.
#define FSTRIDE 136

// ---------------- K1: KNN (top-16 smallest d2 per point, self included) ----------------
// Branch-free full 16-level predicated bubble (round-8 winning version).
__global__ void knn_kernel(const float* __restrict__ p) {
    __shared__ __align__(16) float4 sp[1024];   // (x, y, z, |p|^2)
    const int cloud = blockIdx.y;
    const int q     = blockIdx.x * 128 + threadIdx.x;
    const int gi    = cloud * MM + q;

    const float qx = p[gi*3+0], qy = p[gi*3+1], qz = p[gi*3+2];
    const float qx2 = -2.f*qx, qy2 = -2.f*qy, qz2 = -2.f*qz;

    float dk[KNB]; int ik[KNB];
    #pragma unroll
    for (int t = 0; t < KNB; t++) { dk[t] = 3.0e38f; ik[t] = 0; }

    for (int t0 = 0; t0 < MM; t0 += 1024) {
        for (int jj = threadIdx.x; jj < 1024; jj += 128) {
            const int gj = cloud * MM + t0 + jj;
            float a = p[gj*3+0], b = p[gj*3+1], c = p[gj*3+2];
            sp[jj] = make_float4(a, b, c, a*a + b*b + c*c);
        }
        __syncthreads();
        #pragma unroll 4
        for (int jj = 0; jj < 1024; jj++) {
            const float4 s = sp[jj];
            float d = fmaf(qx2, s.x, fmaf(qy2, s.y, fmaf(qz2, s.z, s.w)));
            if (d < dk[KNB-1]) {
                float cd = d; int ci = t0 + jj;
                #pragma unroll
                for (int t = 0; t < KNB; t++) {
                    const float lo  = fminf(cd, dk[t]);
                    const float hiv = fmaxf(cd, dk[t]);
                    const bool  sw  = cd < dk[t];
                    const int   niv = sw ? ik[t] : ci;
                    ik[t] = sw ? ci : ik[t];
                    dk[t] = lo;
                    cd = hiv; ci = niv;
                }
            }
        }
        __syncthreads();
    }
    #pragma unroll
    for (int t = 0; t < KNB; t++) g_idx[gi*KNB + t] = ik[t];
}

// ---------------- K2: u = [p,x] @ w1 (67x64), v = p @ w1[0:3] ----------------
__global__ void uv_kernel(const float* __restrict__ p, const float* __restrict__ x,
                          const float* __restrict__ w1) {
    __shared__ __align__(16) float ws[67*64];
    __shared__ float as[64*68];
    const int tid  = threadIdx.x;
    const int row0 = blockIdx.x * 64;

    for (int i = tid; i < 67*64; i += 256) ws[i] = w1[i];
    for (int i = tid; i < 64*3; i += 256) {
        int rl = i / 3, cc = i % 3;
        as[rl*68 + cc] = p[(row0 + rl)*3 + cc];
    }
    for (int i = tid; i < 64*64; i += 256) {
        int rl = i >> 6, cc = i & 63;
        as[rl*68 + 3 + cc] = x[(row0 + rl)*64 + cc];
    }
    __syncthreads();

    const int rl = tid >> 2;
    const int c0 = (tid & 3) * 16;
    float acc[16];
    #pragma unroll
    for (int d = 0; d < 16; d++) acc[d] = 0.f;

    #pragma unroll
    for (int c = 0; c < 3; c++) {                 // xyz part -> becomes v
        float a = as[rl*68 + c];
        const float4* wp = (const float4*)&ws[c*64 + c0];
        #pragma unroll
        for (int d4 = 0; d4 < 4; d4++) {
            float4 w = wp[d4];
            acc[d4*4+0] = fmaf(a, w.x, acc[d4*4+0]);
            acc[d4*4+1] = fmaf(a, w.y, acc[d4*4+1]);
            acc[d4*4+2] = fmaf(a, w.z, acc[d4*4+2]);
            acc[d4*4+3] = fmaf(a, w.w, acc[d4*4+3]);
        }
    }
    float vac[16];
    #pragma unroll
    for (int d = 0; d < 16; d++) vac[d] = acc[d];

    for (int c = 3; c < 67; c++) {                // feature part
        float a = as[rl*68 + c];
        const float4* wp = (const float4*)&ws[c*64 + c0];
        #pragma unroll
        for (int d4 = 0; d4 < 4; d4++) {
            float4 w = wp[d4];
            acc[d4*4+0] = fmaf(a, w.x, acc[d4*4+0]);
            acc[d4*4+1] = fmaf(a, w.y, acc[d4*4+1]);
            acc[d4*4+2] = fmaf(a, w.z, acc[d4*4+2]);
            acc[d4*4+3] = fmaf(a, w.w, acc[d4*4+3]);
        }
    }
    const int grow = row0 + rl;
    float4* up = (float4*)&g_u[grow*64 + c0];
    float4* vp = (float4*)&g_v[grow*64 + c0];
    #pragma unroll
    for (int d4 = 0; d4 < 4; d4++) {
        up[d4] = make_float4(acc[d4*4], acc[d4*4+1], acc[d4*4+2], acc[d4*4+3]);
        vp[d4] = make_float4(vac[d4*4], vac[d4*4+1], vac[d4*4+2], vac[d4*4+3]);
    }
}

// ---------------- K3: BN statistics + fused final reduce (last-block pattern) ----
__global__ void stats_kernel(const float* __restrict__ gamma,
                             const float* __restrict__ beta) {
    __shared__ float s_sum[SPB*64];
    __shared__ float s_ss[SPB*64];
    __shared__ bool  s_last;
    const int tid  = threadIdx.x;
    const int pt   = tid >> 2;
    const int c0   = (tid & 3) * 16;
    const int i    = blockIdx.x * SPB + pt;
    const int cloud = i >> 12;

    float4 v4[4];
    #pragma unroll
    for (int q = 0; q < 4; q++) v4[q] = *(const float4*)&g_v[i*64 + c0 + q*4];

    float sum[16], ss[16];
    #pragma unroll
    for (int d = 0; d < 16; d++) { sum[d] = 0.f; ss[d] = 0.f; }

    #pragma unroll 4
    for (int kk = 0; kk < KNB; kk++) {
        int j = g_idx[i*KNB + kk];
        const float4* up = (const float4*)&g_u[((cloud << 12) + j)*64 + c0];
        #pragma unroll
        for (int q = 0; q < 4; q++) {
            float4 u4 = up[q];
            float h0 = u4.x - v4[q].x, h1 = u4.y - v4[q].y;
            float h2 = u4.z - v4[q].z, h3 = u4.w - v4[q].w;
            sum[q*4+0] += h0; sum[q*4+1] += h1; sum[q*4+2] += h2; sum[q*4+3] += h3;
            ss[q*4+0] += h0*h0; ss[q*4+1] += h1*h1; ss[q*4+2] += h2*h2; ss[q*4+3] += h3*h3;
        }
    }
    #pragma unroll
    for (int d = 0; d < 16; d++) {
        s_sum[pt*64 + c0 + d] = sum[d];
        s_ss [pt*64 + c0 + d] = ss[d];
    }
    __syncthreads();

    if (tid < 128) {
        const int ch  = tid & 63;
        const bool hi = tid >= 64;
        float a = 0.f;
        #pragma unroll 8
        for (int p2 = 0; p2 < SPB; p2++)
            a += hi ? s_ss[p2*64 + ch] : s_sum[p2*64 + ch];
        g_partial[blockIdx.x*128 + tid] = a;
    }
    __threadfence();
    __syncthreads();
    if (tid == 0) s_last = (atomicAdd(&g_tick, 1u) == (unsigned)(NSB - 1));
    __syncthreads();
    if (!s_last) return;

    {
        const int col = tid & 127;
        const int grp = tid >> 7;
        float a = 0.f;
        #pragma unroll 8
        for (int r = grp * (NSB/2); r < (grp + 1) * (NSB/2); r++)
            a += g_partial[r*128 + col];
        s_sum[grp*128 + col] = a;
    }
    __syncthreads();
    if (tid < 64) {
        const float inv_n = 1.f / (float)NPOS;
        float mean = (s_sum[tid]      + s_sum[128 + tid]) * inv_n;
        float sq   = (s_sum[64 + tid] + s_sum[192 + tid]) * inv_n;
        float var  = sq - mean*mean;
        float sc   = gamma[tid] * rsqrtf(var + EPSF);
        g_scale[tid] = sc;
        g_shift[tid] = beta[tid] - mean * sc;
    }
    if (tid == 0) g_tick = 0u;   // reset for next graph replay
}

// ---------------- K4: fused BN+ReLU + GEMM2 (64->128) + maxpool via TF32 MMA ------
// 8 points/block, 8 warps. Warp tile M=32 x N=64: warp (wm,wn) handles points
// {2wm, 2wm+1} and N-cols [wn*64, wn*64+64). Per k-chunk: 8 A-LDS + 16 B-LDS
// for 16 MMAs (1.5 LDS/MMA vs 2.25 before). FSTRIDE keeps loads conflict-free.
__global__ void __launch_bounds__(256) out_kernel(const float* __restrict__ w2,
                                                  const float* __restrict__ b2,
                                                  float* __restrict__ out) {
    extern __shared__ float sm[];
    uint32_t* w2s = (uint32_t*)sm;                    // [64][FSTRIDE] tf32
    uint32_t* hs  = (uint32_t*)(sm + 64*FSTRIDE);     // [64][FSTRIDE] tf32 (k-major)
    float* ssc = sm + 2*64*FSTRIDE;                   // 64
    float* ssh = ssc + 64;                            // 64

    const int t = threadIdx.x;
    for (int i = t; i < 8192; i += 256) {
        int k = i >> 7, n = i & 127;
        w2s[k*FSTRIDE + n] = f2tf32(w2[i]);
    }
    if (t < 64)        ssc[t]      = g_scale[t];
    else if (t < 128)  ssh[t - 64] = g_shift[t - 64];
    __syncthreads();

    // Stage 1: build BN+ReLU'd h tile (tf32). thread -> (row = t>>1, 32-channel half)
    {
        const int row = t >> 1;
        const int c0  = (t & 1) * 32;
        const int ptl = row >> 4;
        const int kk  = row & 15;
        const int i   = blockIdx.x * 8 + ptl;
        const int cloud = i >> 12;
        const int j   = g_idx[i*KNB + kk];
        const int ur  = (cloud << 12) + j;
        const float4* up = (const float4*)&g_u[ur*64 + c0];
        const float4* vp = (const float4*)&g_v[i*64 + c0];
        #pragma unroll
        for (int q = 0; q < 8; q++) {
            float4 uu = up[q];
            float4 vv = vp[q];
            int c = c0 + q*4;
            hs[(c+0)*FSTRIDE + row] = f2tf32(fmaxf(fmaf(ssc[c+0], uu.x - vv.x, ssh[c+0]), 0.f));
            hs[(c+1)*FSTRIDE + row] = f2tf32(fmaxf(fmaf(ssc[c+1], uu.y - vv.y, ssh[c+1]), 0.f));
            hs[(c+2)*FSTRIDE + row] = f2tf32(fmaxf(fmaf(ssc[c+2], uu.z - vv.z, ssh[c+2]), 0.f));
            hs[(c+3)*FSTRIDE + row] = f2tf32(fmaxf(fmaf(ssc[c+3], uu.w - vv.w, ssh[c+3]), 0.f));
        }
    }
    __syncthreads();

    // Stage 2: per-warp 32x64x64 TF32 MMA (2 points x 8 N-tiles)
    const int w    = t >> 5;
    const int lane = t & 31;
    const int grp  = lane >> 2;       // row group 0..7
    const int lid4 = lane & 3;        // k/col group 0..3
    const int wm   = w >> 1;          // point-pair 0..3
    const int wn   = w & 1;           // N-half 0..1
    const int rbase  = wm * 32;       // rows for points 2wm, 2wm+1
    const int ntbase = wn * 8;        // N-tiles [ntbase, ntbase+8)

    float acc0[8][4], acc1[8][4];
    #pragma unroll
    for (int nt = 0; nt < 8; nt++)
        #pragma unroll
        for (int e = 0; e < 4; e++) { acc0[nt][e] = 0.f; acc1[nt][e] = 0.f; }

    #pragma unroll
    for (int kc = 0; kc < 8; kc++) {
        const int c0 = kc * 8;
        const uint32_t* hrow0 = hs + (c0 + lid4    )*FSTRIDE + rbase + grp;
        const uint32_t* hrow1 = hs + (c0 + lid4 + 4)*FSTRIDE + rbase + grp;
        const uint32_t a00 = hrow0[0],  a01 = hrow0[8];
        const uint32_t a02 = hrow1[0],  a03 = hrow1[8];
        const uint32_t a10 = hrow0[16], a11 = hrow0[24];
        const uint32_t a12 = hrow1[16], a13 = hrow1[24];
        #pragma unroll
        for (int nt = 0; nt < 8; nt++) {
            const int ncol = (ntbase + nt)*8 + grp;
            const uint32_t b0 = w2s[(c0 + lid4    )*FSTRIDE + ncol];
            const uint32_t b1 = w2s[(c0 + lid4 + 4)*FSTRIDE + ncol];
            mma_tf32(acc0[nt], a00, a01, a02, a03, b0, b1);
            mma_tf32(acc1[nt], a10, a11, a12, a13, b0, b1);
        }
    }

    // Stage 3: maxpool over each point's 16 rows + store
    const int i0 = blockIdx.x * 8 + 2*wm;
    #pragma unroll
    for (int pt = 0; pt < 2; pt++) {
        const int oi = i0 + pt;
        #pragma unroll
        for (int nt = 0; nt < 8; nt++) {
            float* a = pt ? acc1[nt] : acc0[nt];
            float m0 = fmaxf(a[0], a[2]);
            float m1 = fmaxf(a[1], a[3]);
            #pragma unroll
            for (int mask = 4; mask <= 16; mask <<= 1) {
                m0 = fmaxf(m0, __shfl_xor_sync(0xFFFFFFFFu, m0, mask));
                m1 = fmaxf(m1, __shfl_xor_sync(0xFFFFFFFFu, m1, mask));
            }
            if (grp == 0) {
                const int col = (ntbase + nt)*8 + 2*lid4;
                float2 o;
                o.x = m0 + __ldg(&b2[col]);
                o.y = m1 + __ldg(&b2[col + 1]);
                *(float2*)&out[oi*128 + col] = o;
            }
        }
    }
}

// ---------------- launcher ----------------
extern "C" void kernel_launch(void* const* d_in, const int* in_sizes, int n_in,
                              void* d_out, int out_size) {
    const float* p     = (const float*)d_in[0];
    const float* x     = (const float*)d_in[1];
    const float* w1    = (const float*)d_in[2];
    const float* gamma = (const float*)d_in[3];
    const float* beta  = (const float*)d_in[4];
    const float* w2    = (const float*)d_in[5];
    const float* b2    = (const float*)d_in[6];
    float* out = (float*)d_out;

    (void)in_sizes; (void)n_in; (void)out_size;

    // smem: 2*64*136 + 128 = 17536 floats = 70144 B
    cudaFuncSetAttribute(out_kernel, cudaFuncAttributeMaxDynamicSharedMemorySize, 70144);

    knn_kernel<<<dim3(MM/128, BB), 128>>>(p);
    uv_kernel<<<NPTS/64, 256>>>(p, x, w1);
    stats_kernel<<<NSB, 256>>>(gamma, beta);
    out_kernel<<<NPTS/8, 256, 70144>>>(w2, b2, out);
}

// round 13
// speedup vs baseline: 1.4348x; 1.2007x over previous
#include <cuda_runtime.h>
#include <cstdint>

// Problem constants
#define BB    16
#define MM    4096
#define KNB   16          // nsample
#define CMID  64          // c_out/2
#define COUT  128
#define NPTS  (BB*MM)     // 65536 points
#define NPOS  (NPTS*KNB)  // 1048576 BN positions
#define EPSF  1e-5f
#define SPB   64          // stats points per block
#define NSB   (NPTS/SPB)  // 1024 stats blocks

// Scratch (static device globals — no runtime allocation)
__device__ int   g_idx[NPOS];            // 4 MB  per-cloud neighbor indices (0..4095)
__device__ float g_u[NPTS*CMID];         // 16 MB u_j = [p_j,x_j] @ w1
__device__ float g_v[NPTS*CMID];         // 16 MB v_i = p_i @ w1[0:3]
__device__ float g_partial[NSB*128];     // per-block [sum(64) | sumsq(64)]
__device__ float g_scale[CMID];
__device__ float g_shift[CMID];
__device__ unsigned int g_tick;          // zero-init; reset by last block each call

// ---------------- tf32 helpers ----------------
__device__ __forceinline__ uint32_t f2tf32(float f) {
    uint32_t u;
    asm("cvt.rna.tf32.f32 %0, %1;" : "=r"(u) : "f"(f));
    return u;
}
__device__ __forceinline__ void mma_tf32(float* d,
                                         uint32_t a0, uint32_t a1, uint32_t a2, uint32_t a3,
                                         uint32_t b0, uint32_t b1) {
    asm volatile(
        "mma.sync.aligned.m16n8k8.row.col.f32.tf32.tf32.f32 "
        "{%0,%1,%2,%3}, {%4,%5,%6,%7}, {%8,%9}, {%0,%1,%2,%3};"
        : "+f"(d[0]), "+f"(d[1]), "+f"(d[2]), "+f"(d[3])
        : "r"(a0), "r"(a1), "r"(a2), "r"(a3), "r"(b0), "r"(b1));
}

// Fragment-row stride: 136 mod 32 = 8 -> lane bank = 8*lid4 + grp, a bijection
// over lid4 in [0,4) x grp in [0,8): conflict-free fragment loads.
#define FSTRIDE 136

// ---------------- K1: KNN (top-16 smallest d2 per point, self included) ----------------
// Flattened O(1)-depth sorted insert: 16 independent compares, then per-slot
// selects using only OLD values (written descending t). Chain ~12 cyc vs ~128
// for the bubble. Selected set + order identical to the bubble version.
__global__ void knn_kernel(const float* __restrict__ p) {
    __shared__ __align__(16) float4 sp[1024];   // (x, y, z, |p|^2)
    const int cloud = blockIdx.y;
    const int q     = blockIdx.x * 128 + threadIdx.x;
    const int gi    = cloud * MM + q;

    const float qx = p[gi*3+0], qy = p[gi*3+1], qz = p[gi*3+2];
    const float qx2 = -2.f*qx, qy2 = -2.f*qy, qz2 = -2.f*qz;

    float dk[KNB]; int ik[KNB];
    #pragma unroll
    for (int t = 0; t < KNB; t++) { dk[t] = 3.0e38f; ik[t] = 0; }

    for (int t0 = 0; t0 < MM; t0 += 1024) {
        for (int jj = threadIdx.x; jj < 1024; jj += 128) {
            const int gj = cloud * MM + t0 + jj;
            float a = p[gj*3+0], b = p[gj*3+1], c = p[gj*3+2];
            sp[jj] = make_float4(a, b, c, a*a + b*b + c*c);
        }
        __syncthreads();
        #pragma unroll 4
        for (int jj = 0; jj < 1024; jj++) {
            const float4 s = sp[jj];
            float d = fmaf(qx2, s.x, fmaf(qy2, s.y, fmaf(qz2, s.z, s.w)));
            if (d < dk[KNB-1]) {
                const int ci = t0 + jj;
                bool c[KNB];
                #pragma unroll
                for (int t = 0; t < KNB; t++) c[t] = (dk[t] <= d);
                #pragma unroll
                for (int t = KNB-1; t >= 1; --t) {
                    dk[t] = c[t] ? dk[t] : (c[t-1] ? d  : dk[t-1]);
                    ik[t] = c[t] ? ik[t] : (c[t-1] ? ci : ik[t-1]);
                }
                dk[0] = c[0] ? dk[0] : d;
                ik[0] = c[0] ? ik[0] : ci;
            }
        }
        __syncthreads();
    }
    #pragma unroll
    for (int t = 0; t < KNB; t++) g_idx[gi*KNB + t] = ik[t];
}

// ---------------- K2: u = [p,x] @ w1 (67x64), v = p @ w1[0:3] ----------------
__global__ void uv_kernel(const float* __restrict__ p, const float* __restrict__ x,
                          const float* __restrict__ w1) {
    __shared__ __align__(16) float ws[67*64];
    __shared__ float as[64*68];
    const int tid  = threadIdx.x;
    const int row0 = blockIdx.x * 64;

    for (int i = tid; i < 67*64; i += 256) ws[i] = w1[i];
    for (int i = tid; i < 64*3; i += 256) {
        int rl = i / 3, cc = i % 3;
        as[rl*68 + cc] = p[(row0 + rl)*3 + cc];
    }
    for (int i = tid; i < 64*64; i += 256) {
        int rl = i >> 6, cc = i & 63;
        as[rl*68 + 3 + cc] = x[(row0 + rl)*64 + cc];
    }
    __syncthreads();

    const int rl = tid >> 2;
    const int c0 = (tid & 3) * 16;
    float acc[16];
    #pragma unroll
    for (int d = 0; d < 16; d++) acc[d] = 0.f;

    #pragma unroll
    for (int c = 0; c < 3; c++) {                 // xyz part -> becomes v
        float a = as[rl*68 + c];
        const float4* wp = (const float4*)&ws[c*64 + c0];
        #pragma unroll
        for (int d4 = 0; d4 < 4; d4++) {
            float4 w = wp[d4];
            acc[d4*4+0] = fmaf(a, w.x, acc[d4*4+0]);
            acc[d4*4+1] = fmaf(a, w.y, acc[d4*4+1]);
            acc[d4*4+2] = fmaf(a, w.z, acc[d4*4+2]);
            acc[d4*4+3] = fmaf(a, w.w, acc[d4*4+3]);
        }
    }
    float vac[16];
    #pragma unroll
    for (int d = 0; d < 16; d++) vac[d] = acc[d];

    for (int c = 3; c < 67; c++) {                // feature part
        float a = as[rl*68 + c];
        const float4* wp = (const float4*)&ws[c*64 + c0];
        #pragma unroll
        for (int d4 = 0; d4 < 4; d4++) {
            float4 w = wp[d4];
            acc[d4*4+0] = fmaf(a, w.x, acc[d4*4+0]);
            acc[d4*4+1] = fmaf(a, w.y, acc[d4*4+1]);
            acc[d4*4+2] = fmaf(a, w.z, acc[d4*4+2]);
            acc[d4*4+3] = fmaf(a, w.w, acc[d4*4+3]);
        }
    }
    const int grow = row0 + rl;
    float4* up = (float4*)&g_u[grow*64 + c0];
    float4* vp = (float4*)&g_v[grow*64 + c0];
    #pragma unroll
    for (int d4 = 0; d4 < 4; d4++) {
        up[d4] = make_float4(acc[d4*4], acc[d4*4+1], acc[d4*4+2], acc[d4*4+3]);
        vp[d4] = make_float4(vac[d4*4], vac[d4*4+1], vac[d4*4+2], vac[d4*4+3]);
    }
}

// ---------------- K3: BN statistics + fused final reduce (last-block pattern) ----
__global__ void stats_kernel(const float* __restrict__ gamma,
                             const float* __restrict__ beta) {
    __shared__ float s_sum[SPB*64];
    __shared__ float s_ss[SPB*64];
    __shared__ bool  s_last;
    const int tid  = threadIdx.x;
    const int pt   = tid >> 2;
    const int c0   = (tid & 3) * 16;
    const int i    = blockIdx.x * SPB + pt;
    const int cloud = i >> 12;

    float4 v4[4];
    #pragma unroll
    for (int q = 0; q < 4; q++) v4[q] = *(const float4*)&g_v[i*64 + c0 + q*4];

    float sum[16], ss[16];
    #pragma unroll
    for (int d = 0; d < 16; d++) { sum[d] = 0.f; ss[d] = 0.f; }

    #pragma unroll 4
    for (int kk = 0; kk < KNB; kk++) {
        int j = g_idx[i*KNB + kk];
        const float4* up = (const float4*)&g_u[((cloud << 12) + j)*64 + c0];
        #pragma unroll
        for (int q = 0; q < 4; q++) {
            float4 u4 = up[q];
            float h0 = u4.x - v4[q].x, h1 = u4.y - v4[q].y;
            float h2 = u4.z - v4[q].z, h3 = u4.w - v4[q].w;
            sum[q*4+0] += h0; sum[q*4+1] += h1; sum[q*4+2] += h2; sum[q*4+3] += h3;
            ss[q*4+0] += h0*h0; ss[q*4+1] += h1*h1; ss[q*4+2] += h2*h2; ss[q*4+3] += h3*h3;
        }
    }
    #pragma unroll
    for (int d = 0; d < 16; d++) {
        s_sum[pt*64 + c0 + d] = sum[d];
        s_ss [pt*64 + c0 + d] = ss[d];
    }
    __syncthreads();

    if (tid < 128) {
        const int ch  = tid & 63;
        const bool hi = tid >= 64;
        float a = 0.f;
        #pragma unroll 8
        for (int p2 = 0; p2 < SPB; p2++)
            a += hi ? s_ss[p2*64 + ch] : s_sum[p2*64 + ch];
        g_partial[blockIdx.x*128 + tid] = a;
    }
    __threadfence();
    __syncthreads();
    if (tid == 0) s_last = (atomicAdd(&g_tick, 1u) == (unsigned)(NSB - 1));
    __syncthreads();
    if (!s_last) return;

    {
        const int col = tid & 127;
        const int grp = tid >> 7;
        float a = 0.f;
        #pragma unroll 8
        for (int r = grp * (NSB/2); r < (grp + 1) * (NSB/2); r++)
            a += g_partial[r*128 + col];
        s_sum[grp*128 + col] = a;
    }
    __syncthreads();
    if (tid < 64) {
        const float inv_n = 1.f / (float)NPOS;
        float mean = (s_sum[tid]      + s_sum[128 + tid]) * inv_n;
        float sq   = (s_sum[64 + tid] + s_sum[192 + tid]) * inv_n;
        float var  = sq - mean*mean;
        float sc   = gamma[tid] * rsqrtf(var + EPSF);
        g_scale[tid] = sc;
        g_shift[tid] = beta[tid] - mean * sc;
    }
    if (tid == 0) g_tick = 0u;   // reset for next graph replay
}

// ---------------- K4: fused BN+ReLU + GEMM2 (64->128) + maxpool via TF32 MMA ------
// 8 points/block, 8 warps. Warp tile M=32 x N=64 (round-12 282us version).
__global__ void __launch_bounds__(256) out_kernel(const float* __restrict__ w2,
                                                  const float* __restrict__ b2,
                                                  float* __restrict__ out) {
    extern __shared__ float sm[];
    uint32_t* w2s = (uint32_t*)sm;                    // [64][FSTRIDE] tf32
    uint32_t* hs  = (uint32_t*)(sm + 64*FSTRIDE);     // [64][FSTRIDE] tf32 (k-major)
    float* ssc = sm + 2*64*FSTRIDE;                   // 64
    float* ssh = ssc + 64;                            // 64

    const int t = threadIdx.x;
    for (int i = t; i < 8192; i += 256) {
        int k = i >> 7, n = i & 127;
        w2s[k*FSTRIDE + n] = f2tf32(w2[i]);
    }
    if (t < 64)        ssc[t]      = g_scale[t];
    else if (t < 128)  ssh[t - 64] = g_shift[t - 64];
    __syncthreads();

    // Stage 1: build BN+ReLU'd h tile (tf32). thread -> (row = t>>1, 32-channel half)
    {
        const int row = t >> 1;
        const int c0  = (t & 1) * 32;
        const int ptl = row >> 4;
        const int kk  = row & 15;
        const int i   = blockIdx.x * 8 + ptl;
        const int cloud = i >> 12;
        const int j   = g_idx[i*KNB + kk];
        const int ur  = (cloud << 12) + j;
        const float4* up = (const float4*)&g_u[ur*64 + c0];
        const float4* vp = (const float4*)&g_v[i*64 + c0];
        #pragma unroll
        for (int q = 0; q < 8; q++) {
            float4 uu = up[q];
            float4 vv = vp[q];
            int c = c0 + q*4;
            hs[(c+0)*FSTRIDE + row] = f2tf32(fmaxf(fmaf(ssc[c+0], uu.x - vv.x, ssh[c+0]), 0.f));
            hs[(c+1)*FSTRIDE + row] = f2tf32(fmaxf(fmaf(ssc[c+1], uu.y - vv.y, ssh[c+1]), 0.f));
            hs[(c+2)*FSTRIDE + row] = f2tf32(fmaxf(fmaf(ssc[c+2], uu.z - vv.z, ssh[c+2]), 0.f));
            hs[(c+3)*FSTRIDE + row] = f2tf32(fmaxf(fmaf(ssc[c+3], uu.w - vv.w, ssh[c+3]), 0.f));
        }
    }
    __syncthreads();

    // Stage 2: per-warp 32x64x64 TF32 MMA (2 points x 8 N-tiles)
    const int w    = t >> 5;
    const int lane = t & 31;
    const int grp  = lane >> 2;       // row group 0..7
    const int lid4 = lane & 3;        // k/col group 0..3
    const int wm   = w >> 1;          // point-pair 0..3
    const int wn   = w & 1;           // N-half 0..1
    const int rbase  = wm * 32;       // rows for points 2wm, 2wm+1
    const int ntbase = wn * 8;        // N-tiles [ntbase, ntbase+8)

    float acc0[8][4], acc1[8][4];
    #pragma unroll
    for (int nt = 0; nt < 8; nt++)
        #pragma unroll
        for (int e = 0; e < 4; e++) { acc0[nt][e] = 0.f; acc1[nt][e] = 0.f; }

    #pragma unroll
    for (int kc = 0; kc < 8; kc++) {
        const int c0 = kc * 8;
        const uint32_t* hrow0 = hs + (c0 + lid4    )*FSTRIDE + rbase + grp;
        const uint32_t* hrow1 = hs + (c0 + lid4 + 4)*FSTRIDE + rbase + grp;
        const uint32_t a00 = hrow0[0],  a01 = hrow0[8];
        const uint32_t a02 = hrow1[0],  a03 = hrow1[8];
        const uint32_t a10 = hrow0[16], a11 = hrow0[24];
        const uint32_t a12 = hrow1[16], a13 = hrow1[24];
        #pragma unroll
        for (int nt = 0; nt < 8; nt++) {
            const int ncol = (ntbase + nt)*8 + grp;
            const uint32_t b0 = w2s[(c0 + lid4    )*FSTRIDE + ncol];
            const uint32_t b1 = w2s[(c0 + lid4 + 4)*FSTRIDE + ncol];
            mma_tf32(acc0[nt], a00, a01, a02, a03, b0, b1);
            mma_tf32(acc1[nt], a10, a11, a12, a13, b0, b1);
        }
    }

    // Stage 3: maxpool over each point's 16 rows + store
    const int i0 = blockIdx.x * 8 + 2*wm;
    #pragma unroll
    for (int pt = 0; pt < 2; pt++) {
        const int oi = i0 + pt;
        #pragma unroll
        for (int nt = 0; nt < 8; nt++) {
            float* a = pt ? acc1[nt] : acc0[nt];
            float m0 = fmaxf(a[0], a[2]);
            float m1 = fmaxf(a[1], a[3]);
            #pragma unroll
            for (int mask = 4; mask <= 16; mask <<= 1) {
                m0 = fmaxf(m0, __shfl_xor_sync(0xFFFFFFFFu, m0, mask));
                m1 = fmaxf(m1, __shfl_xor_sync(0xFFFFFFFFu, m1, mask));
            }
            if (grp == 0) {
                const int col = (ntbase + nt)*8 + 2*lid4;
                float2 o;
                o.x = m0 + __ldg(&b2[col]);
                o.y = m1 + __ldg(&b2[col + 1]);
                *(float2*)&out[oi*128 + col] = o;
            }
        }
    }
}

// ---------------- launcher ----------------
extern "C" void kernel_launch(void* const* d_in, const int* in_sizes, int n_in,
                              void* d_out, int out_size) {
    const float* p     = (const float*)d_in[0];
    const float* x     = (const float*)d_in[1];
    const float* w1    = (const float*)d_in[2];
    const float* gamma = (const float*)d_in[3];
    const float* beta  = (const float*)d_in[4];
    const float* w2    = (const float*)d_in[5];
    const float* b2    = (const float*)d_in[6];
    float* out = (float*)d_out;

    (void)in_sizes; (void)n_in; (void)out_size;

    // smem: 2*64*136 + 128 = 17536 floats = 70144 B
    cudaFuncSetAttribute(out_kernel, cudaFuncAttributeMaxDynamicSharedMemorySize, 70144);

    knn_kernel<<<dim3(MM/128, BB), 128>>>(p);
    uv_kernel<<<NPTS/64, 256>>>(p, x, w1);
    stats_kernel<<<NSB, 256>>>(gamma, beta);
    out_kernel<<<NPTS/8, 256, 70144>>>(w2, b2, out);
}